// round 2
// baseline (speedup 1.0000x reference)
#include <cuda_runtime.h>
#include <stdint.h>

// atom_eng[c] = FACTOR * sum_{edges e with center c} edge_eng[e] * scales[sp[c], sp[nbr]]
// E = 6.4M, N = 100K, scales 16x16. Harness narrows int64 inputs to int32.

#define FACTOR 0.125f  // 1/sqrt(64)

__global__ void zero_out_kernel(float* __restrict__ out, int n) {
    int i = blockIdx.x * blockDim.x + threadIdx.x;
    if (i < n) out[i] = 0.0f;
}

__global__ __launch_bounds__(256) void edge_energy_sum_kernel(
    const float* __restrict__ edge_eng,     // [E]
    const float* __restrict__ scales,       // [256]
    const int*   __restrict__ ei_center,    // [E]
    const int*   __restrict__ ei_neighbor,  // [E]
    const int*   __restrict__ species,      // [N]
    float* __restrict__ out,                // [N]
    int E)
{
    __shared__ float s_scale[256];
    if (threadIdx.x < 256) s_scale[threadIdx.x] = scales[threadIdx.x] * FACTOR;
    __syncthreads();

    int nvec = E >> 2;
    int tid = blockIdx.x * blockDim.x + threadIdx.x;
    int stride = gridDim.x * blockDim.x;

    const float4* eng4 = (const float4*)edge_eng;
    const int4*   c4   = (const int4*)ei_center;
    const int4*   n4   = (const int4*)ei_neighbor;

    for (int v = tid; v < nvec; v += stride) {
        float4 e = eng4[v];
        int4 c = c4[v];
        int4 n = n4[v];

        int sc0 = __ldg(&species[c.x]);
        int sc1 = __ldg(&species[c.y]);
        int sc2 = __ldg(&species[c.z]);
        int sc3 = __ldg(&species[c.w]);
        int sn0 = __ldg(&species[n.x]);
        int sn1 = __ldg(&species[n.y]);
        int sn2 = __ldg(&species[n.z]);
        int sn3 = __ldg(&species[n.w]);

        float v0 = e.x * s_scale[(sc0 << 4) | sn0];
        float v1 = e.y * s_scale[(sc1 << 4) | sn1];
        float v2 = e.z * s_scale[(sc2 << 4) | sn2];
        float v3 = e.w * s_scale[(sc3 << 4) | sn3];

        atomicAdd(&out[c.x], v0);
        atomicAdd(&out[c.y], v1);
        atomicAdd(&out[c.z], v2);
        atomicAdd(&out[c.w], v3);
    }

    // Scalar tail
    int base = nvec << 2;
    for (int i = base + tid; i < E; i += stride) {
        int c = ei_center[i];
        int nn = ei_neighbor[i];
        int sc = __ldg(&species[c]);
        int sn = __ldg(&species[nn]);
        float val = edge_eng[i] * s_scale[(sc << 4) | sn];
        atomicAdd(&out[c], val);
    }
}

extern "C" void kernel_launch(void* const* d_in, const int* in_sizes, int n_in,
                              void* d_out, int out_size) {
    const float* edge_eng = (const float*)d_in[0];  // [E,1]
    const float* scales   = (const float*)d_in[1];  // [16,16]
    const int*   edge_idx = (const int*)d_in[2];    // [2,E] (narrowed to int32)
    const int*   species  = (const int*)d_in[3];    // [N]
    float* out = (float*)d_out;

    int E = in_sizes[0];   // edge_eng element count = E
    int N = out_size;

    const int* ei_center   = edge_idx;
    const int* ei_neighbor = edge_idx + E;

    zero_out_kernel<<<(N + 255) / 256, 256>>>(out, N);

    int nvec = E >> 2;
    int threads = 256;
    int blocks = (nvec + threads - 1) / threads;
    if (blocks > 148 * 16) blocks = 148 * 16;
    if (blocks < 1) blocks = 1;
    edge_energy_sum_kernel<<<blocks, threads>>>(
        edge_eng, scales, ei_center, ei_neighbor, species, out, E);
}

// round 3
// speedup vs baseline: 1.3395x; 1.3395x over previous
#include <cuda_runtime.h>
#include <stdint.h>

// atom_eng[c] = FACTOR * sum_{edges e with center c} edge_eng[e] * scales[sp[c], sp[nbr]]
// E = 6.4M, N = 100K, scales 16x16. int64 inputs are narrowed to int32 by the harness.
// Strategy: species fits in 4 bits -> pack into nibbles, stage whole table in SMEM,
// eliminating ~410MB of random L2 gather traffic.

#define FACTOR 0.125f  // 1/sqrt(64)

// Scratch for packed species nibbles. 32768 words = up to 262144 nodes.
__device__ uint32_t g_packed_species[32768];

// Fused: zero the output and pack species into nibbles.
__global__ void prep_kernel(const int* __restrict__ species,
                            float* __restrict__ out,
                            int N, int nwords) {
    int i = blockIdx.x * blockDim.x + threadIdx.x;
    if (i < N) out[i] = 0.0f;
    if (i < nwords) {
        uint32_t w = 0;
        int base = i << 3;
        #pragma unroll
        for (int k = 0; k < 8; k++) {
            int idx = base + k;
            if (idx < N) w |= ((uint32_t)species[idx] & 0xFu) << (k << 2);
        }
        g_packed_species[i] = w;
    }
}

__global__ __launch_bounds__(512) void edge_energy_sum_kernel(
    const float* __restrict__ edge_eng,     // [E]
    const float* __restrict__ scales,       // [256]
    const int*   __restrict__ ei_center,    // [E]
    const int*   __restrict__ ei_neighbor,  // [E]
    float* __restrict__ out,                // [N]
    int E, int nwords)
{
    extern __shared__ uint32_t smem[];
    float*    s_scale = (float*)smem;        // 256 floats
    uint32_t* s_pack  = smem + 256;          // nwords words

    if (threadIdx.x < 256) s_scale[threadIdx.x] = scales[threadIdx.x] * FACTOR;
    for (int i = threadIdx.x; i < nwords; i += blockDim.x)
        s_pack[i] = g_packed_species[i];
    __syncthreads();

    int nvec = E >> 2;
    int tid = blockIdx.x * blockDim.x + threadIdx.x;
    int stride = gridDim.x * blockDim.x;

    const float4* eng4 = (const float4*)edge_eng;
    const int4*   c4   = (const int4*)ei_center;
    const int4*   n4   = (const int4*)ei_neighbor;

    for (int v = tid; v < nvec; v += stride) {
        float4 e = eng4[v];
        int4 c = c4[v];
        int4 n = n4[v];

        uint32_t sc0 = (s_pack[c.x >> 3] >> ((c.x & 7) << 2)) & 0xFu;
        uint32_t sc1 = (s_pack[c.y >> 3] >> ((c.y & 7) << 2)) & 0xFu;
        uint32_t sc2 = (s_pack[c.z >> 3] >> ((c.z & 7) << 2)) & 0xFu;
        uint32_t sc3 = (s_pack[c.w >> 3] >> ((c.w & 7) << 2)) & 0xFu;
        uint32_t sn0 = (s_pack[n.x >> 3] >> ((n.x & 7) << 2)) & 0xFu;
        uint32_t sn1 = (s_pack[n.y >> 3] >> ((n.y & 7) << 2)) & 0xFu;
        uint32_t sn2 = (s_pack[n.z >> 3] >> ((n.z & 7) << 2)) & 0xFu;
        uint32_t sn3 = (s_pack[n.w >> 3] >> ((n.w & 7) << 2)) & 0xFu;

        float v0 = e.x * s_scale[(sc0 << 4) | sn0];
        float v1 = e.y * s_scale[(sc1 << 4) | sn1];
        float v2 = e.z * s_scale[(sc2 << 4) | sn2];
        float v3 = e.w * s_scale[(sc3 << 4) | sn3];

        atomicAdd(&out[c.x], v0);
        atomicAdd(&out[c.y], v1);
        atomicAdd(&out[c.z], v2);
        atomicAdd(&out[c.w], v3);
    }

    // Scalar tail
    int base = nvec << 2;
    for (int i = base + tid; i < E; i += stride) {
        int cc = ei_center[i];
        int nn = ei_neighbor[i];
        uint32_t sc = (s_pack[cc >> 3] >> ((cc & 7) << 2)) & 0xFu;
        uint32_t sn = (s_pack[nn >> 3] >> ((nn & 7) << 2)) & 0xFu;
        float val = edge_eng[i] * s_scale[(sc << 4) | sn];
        atomicAdd(&out[cc], val);
    }
}

extern "C" void kernel_launch(void* const* d_in, const int* in_sizes, int n_in,
                              void* d_out, int out_size) {
    const float* edge_eng = (const float*)d_in[0];  // [E,1]
    const float* scales   = (const float*)d_in[1];  // [16,16]
    const int*   edge_idx = (const int*)d_in[2];    // [2,E]
    const int*   species  = (const int*)d_in[3];    // [N]
    float* out = (float*)d_out;

    int E = in_sizes[0];
    int N = out_size;
    int nwords = (N + 7) >> 3;

    const int* ei_center   = edge_idx;
    const int* ei_neighbor = edge_idx + E;

    size_t smem_bytes = 256 * sizeof(float) + (size_t)nwords * sizeof(uint32_t);
    cudaFuncSetAttribute(edge_energy_sum_kernel,
                         cudaFuncAttributeMaxDynamicSharedMemorySize,
                         (int)smem_bytes);

    int prep_n = (N > nwords ? N : nwords);
    prep_kernel<<<(prep_n + 255) / 256, 256>>>(species, out, N, nwords);

    int threads = 512;
    int blocks = 148 * 4;   // 4 CTAs/SM target; grid-stride covers all work
    int nvec = E >> 2;
    int need = (nvec + threads - 1) / threads;
    if (blocks > need) blocks = need > 0 ? need : 1;
    edge_energy_sum_kernel<<<blocks, threads, smem_bytes>>>(
        edge_eng, scales, ei_center, ei_neighbor, out, E, nwords);
}